// round 16
// baseline (speedup 1.0000x reference)
#include <cuda_runtime.h>
#include <cuda_fp16.h>
#include <math.h>

#define S_LEN   2048
#define D_DIM   64
#define TQ      32
#define NBH     32
#define NTHR    512
#define KVSTR   36        // u32 words per token row in SMEM (32 data + 4 pad; LDSM-clean)
#define KVGSTR  32        // u32 words per token row in GMEM scratch (unpadded)
#define REDSTR  68
#define STFSTR  1036      // u32 (half2) words per Stile row

// ---- main-kernel shared memory word offsets ----
#define OFF_Q    0                     // 32*68 = 2176
#define OFF_STF  2176                  // fp16 Stile: 32*1036 = 33152 u32 words
#define ARR_W    4608                  // 128 tokens * 36 words (SMEM, padded)
#define BUF_W    (2*ARR_W)             // Kh,Vh = 9216 words per buffer
#define OFF_BUF  35328                 // two buffers: 2*9216 = 18432
#define OFF_PART (OFF_BUF + 2*BUF_W)   // 53760 : 32 rows * 8 warps
#define OFF_INV  (OFF_PART + 256)      // 54016 : 32
#define SMEM_WORDS (OFF_INV + 32)      // 54048 words = 216192 bytes
#define OFF_RED  OFF_BUF               // O-reduction overlay: 16 warps*16 rows*68 = 17408 <= 18432

// ---- global scratch (single-fp16 K and V, unpadded token rows) ----
__device__ __align__(16) unsigned g_Kh[(size_t)NBH * S_LEN * KVGSTR];
__device__ __align__(16) unsigned g_Vh[(size_t)NBH * S_LEN * KVGSTR];
__device__ unsigned g_mpack[(size_t)S_LEN * (S_LEN / 32)];   // 1 bit per mask elem

static __device__ __forceinline__ unsigned cvt_h2(float x, float y) {
    __half2 hh = __floats2half2_rn(x, y);
    return *reinterpret_cast<unsigned*>(&hh);
}

#define MMA16816(C, A0, A1, A2, A3, B0, B1)                                        \
    asm volatile("mma.sync.aligned.m16n8k16.row.col.f32.f16.f16.f32 "              \
                 "{%0,%1,%2,%3},{%4,%5,%6,%7},{%8,%9},{%0,%1,%2,%3};\n"            \
                 : "+f"(C[0]), "+f"(C[1]), "+f"(C[2]), "+f"(C[3])                  \
                 : "r"(A0), "r"(A1), "r"(A2), "r"(A3), "r"(B0), "r"(B1))

#define LDSM_X4(R0, R1, R2, R3, ADDR)                                              \
    asm volatile("ldmatrix.sync.aligned.m8n8.x4.shared.b16 {%0,%1,%2,%3}, [%4];"  \
                 : "=r"(R0), "=r"(R1), "=r"(R2), "=r"(R3) : "r"(ADDR))

#define LDSM_X4_T(R0, R1, R2, R3, ADDR)                                            \
    asm volatile("ldmatrix.sync.aligned.m8n8.x4.trans.shared.b16 {%0,%1,%2,%3}, [%4];" \
                 : "=r"(R0), "=r"(R1), "=r"(R2), "=r"(R3) : "r"(ADDR))

#define CP_ASYNC16(SADDR, GPTR)                                                    \
    asm volatile("cp.async.cg.shared.global [%0], [%1], 16;\n" :: "r"(SADDR), "l"(GPTR))
#define CP_COMMIT()  asm volatile("cp.async.commit_group;\n")
#define CP_WAIT0()   asm volatile("cp.async.wait_group 0;\n" ::: "memory")

// ===================== pre-pass 1: convert K,V -> fp16 scratch (unpadded) =======
__global__ void __launch_bounds__(256)
preconvert_kv(const float* __restrict__ K, const float* __restrict__ V)
{
    const int bh  = blockIdx.y;
    const int idx = blockIdx.x * 256 + threadIdx.x;
    const int token = idx >> 4, c4 = idx & 15;
    const size_t tok = (size_t)bh * S_LEN + token;
    const size_t go  = tok * KVGSTR + c4 * 2;

    float4 k = __ldg((const float4*)(K + tok * D_DIM) + c4);
    *(uint2*)&g_Kh[go] = make_uint2(cvt_h2(k.x, k.y), cvt_h2(k.z, k.w));
    float4 v = __ldg((const float4*)(V + tok * D_DIM) + c4);
    *(uint2*)&g_Vh[go] = make_uint2(cvt_h2(v.x, v.y), cvt_h2(v.z, v.w));
}

// ===================== pre-pass 2: pack mask to 1 bit/elem ======================
__global__ void __launch_bounds__(256)
pack_mask(const unsigned* __restrict__ M)
{
    const int lane = threadIdx.x & 31;
    const int wglob = (blockIdx.x * 256 + threadIdx.x) >> 5;
    const int nwarps = (gridDim.x * 256) >> 5;
    for (int w = wglob; w < S_LEN * (S_LEN / 32); w += nwarps) {
        unsigned bit = (M[(size_t)w * 32 + lane] != 0u) ? 1u : 0u;
        unsigned word = __ballot_sync(0xffffffffu, bit);
        if (lane == 0) g_mpack[w] = word;
    }
}

// ===================== main fused attention kernel (512 thr, 16 warps) ==========
__global__ void __launch_bounds__(NTHR, 1)
attn_flash_kernel(const float* __restrict__ Q,
                  float* __restrict__ p_val,
                  float* __restrict__ p_attn)
{
    extern __shared__ float smem[];
    unsigned* smw = reinterpret_cast<unsigned*>(smem);
    const unsigned smem_u32 = (unsigned)__cvta_generic_to_shared(smem);

    const int tid  = threadIdx.x;
    const int warp = tid >> 5;          // 0..15
    const int lane = tid & 31;
    const int g    = lane >> 2;
    const int tg   = lane & 3;
    const int m    = warp >> 3;         // m-half: rows m*16 .. m*16+15
    const int wi   = warp & 7;          // token-slice within stage
    const int bh   = blockIdx.y;
    const int q0   = blockIdx.x * TQ;
    const int ln0  = wi * 16;

    // ---- ldmatrix per-lane byte addresses (buffer 0; SMEM stride 36) ----
    const int qk_row  = ln0 + ((lane >> 4) << 3) + (lane & 7);
    const unsigned qk_off = (unsigned)(qk_row * KVSTR + (((lane >> 3) & 1) << 2)) * 4u;
    const unsigned kh_base = smem_u32 + OFF_BUF * 4u + qk_off;
    const int pv_row  = ln0 + (((lane >> 3) & 1) << 3) + (lane & 7);
    const unsigned pv_off = (unsigned)(pv_row * KVSTR + ((lane >> 4) << 2)) * 4u;
    const unsigned vh_base = smem_u32 + (OFF_BUF + ARR_W) * 4u + pv_off;

    // ================= Q tile (32 rows) -> smem -> A fragments (fp16, 1-term) ==
    {
        int row = tid >> 4, c4 = tid & 15;   // 512 threads = 32 rows x 16 f4
        float4 qv = __ldg((const float4*)(Q + ((size_t)bh * S_LEN + q0 + row) * D_DIM) + c4);
        *((float4*)(smem + OFF_Q + row * 68 + c4 * 4)) = qv;
    }
    __syncthreads();

    unsigned qah[4][4];
    {
        int r0 = m * 16 + g, r1 = m * 16 + g + 8;
#pragma unroll
        for (int ks = 0; ks < 4; ks++) {
            int c = ks * 16 + tg * 2;
            float2 x0 = *(const float2*)(smem + OFF_Q + r0 * 68 + c);
            float2 x1 = *(const float2*)(smem + OFF_Q + r1 * 68 + c);
            float2 x2 = *(const float2*)(smem + OFF_Q + r0 * 68 + c + 8);
            float2 x3 = *(const float2*)(smem + OFF_Q + r1 * 68 + c + 8);
            qah[ks][0] = cvt_h2(x0.x, x0.y);
            qah[ks][1] = cvt_h2(x1.x, x1.y);
            qah[ks][2] = cvt_h2(x2.x, x2.y);
            qah[ks][3] = cvt_h2(x3.x, x3.y);
        }
    }

    float rs0 = 0.f, rs1 = 0.f;
    float O[8][4];
#pragma unroll
    for (int j = 0; j < 8; j++) { O[j][0] = O[j][1] = O[j][2] = O[j][3] = 0.f; }

    // mask word pointers (rows m*16+g, m*16+g+8; warp's 16 tokens -> word wi>>1)
    const unsigned* mp0 = g_mpack + (size_t)(q0 + m * 16 + g) * 64 + (wi >> 1);
    const unsigned* mp1 = g_mpack + (size_t)(q0 + m * 16 + g + 8) * 64 + (wi >> 1);
    const unsigned posbase = (wi & 1) * 16;
    const size_t bh_base = (size_t)bh * S_LEN * KVGSTR;
    unsigned* stf = smw + OFF_STF;

    // ---- prologue: issue stage 0 loads (Kh + Vh), gmem unpadded -> smem padded ----
    {
        for (int i = tid; i < 1024; i += NTHR) {
            int row = i >> 3, sub = i & 7;
            unsigned so = (unsigned)(OFF_BUF * 4) + (unsigned)(row * (KVSTR * 4) + sub * 16);
            CP_ASYNC16(smem_u32 + so,             (const uint4*)(g_Kh + bh_base) + i);
            CP_ASYNC16(smem_u32 + so + ARR_W * 4, (const uint4*)(g_Vh + bh_base) + i);
        }
        CP_COMMIT();
    }

    // =================== pipelined main loop: 16 stages of 128 tokens ==========
    for (int st = 0; st < 16; st++) {
        const int kb0 = st * 128;
        const unsigned bufoff = (unsigned)(st & 1) * (BUF_W * 4);

        CP_WAIT0();
        __syncthreads();   // stage-st data visible; prev compute done

        // ---- prefetch stage st+1 into the other buffer ----
        if (st < 15) {
            const size_t sb = bh_base + (size_t)(kb0 + 128) * KVGSTR;
            const unsigned dst = (unsigned)(OFF_BUF * 4) + (unsigned)((st + 1) & 1) * (BUF_W * 4);
            for (int i = tid; i < 1024; i += NTHR) {
                int row = i >> 3, sub = i & 7;
                unsigned so = dst + (unsigned)(row * (KVSTR * 4) + sub * 16);
                CP_ASYNC16(smem_u32 + so,             (const uint4*)(g_Kh + sb) + i);
                CP_ASYNC16(smem_u32 + so + ARR_W * 4, (const uint4*)(g_Vh + sb) + i);
            }
            CP_COMMIT();
        }

        // ---- mask words early ----
        unsigned mw0 = __ldg(mp0 + st * 4);
        unsigned mw1 = __ldg(mp1 + st * 4);

        // ---- QK^T: 1 M-tile x warp's 16 tokens, 1-term Qh·Kh ----
        float C0[4] = {0,0,0,0}, C1[4] = {0,0,0,0};
#pragma unroll
        for (int ks = 0; ks < 4; ks++) {
            unsigned b0, b1, b2, b3;
            LDSM_X4(b0, b1, b2, b3, kh_base + bufoff + ks * 32u);
            MMA16816(C0, qah[ks][0], qah[ks][1], qah[ks][2], qah[ks][3], b0, b1);
            MMA16816(C1, qah[ks][0], qah[ks][1], qah[ks][2], qah[ks][3], b2, b3);
        }

        // ---- epilogue: mask(bit), exp, rowsum ----
        float e[2][4];
#pragma unroll
        for (int t = 0; t < 2; t++) {
            const float* C = t ? C1 : C0;
            unsigned sh = posbase + t * 8 + tg * 2;
            float* E = e[t];
            E[0] = ((mw0 >> sh) & 1u)       ? 0.f : __expf(C[0] * 0.125f);
            E[1] = ((mw0 >> (sh + 1)) & 1u) ? 0.f : __expf(C[1] * 0.125f);
            E[2] = ((mw1 >> sh) & 1u)       ? 0.f : __expf(C[2] * 0.125f);
            E[3] = ((mw1 >> (sh + 1)) & 1u) ? 0.f : __expf(C[3] * 0.125f);
            rs0 += E[0] + E[1];
            rs1 += E[2] + E[3];
        }

        // ---- E -> A-frag fp16; also store to fp16 Stile (smem) ----
        const int colw = st * 64 + wi * 8 + tg;    // half2 word column
        unsigned Ah[4];
        Ah[0] = cvt_h2(e[0][0], e[0][1]);
        Ah[1] = cvt_h2(e[0][2], e[0][3]);
        Ah[2] = cvt_h2(e[1][0], e[1][1]);
        Ah[3] = cvt_h2(e[1][2], e[1][3]);
        {
            unsigned* r0 = stf + (m * 16 + g) * STFSTR;
            unsigned* r1 = stf + (m * 16 + g + 8) * STFSTR;
            r0[colw]     = Ah[0];
            r1[colw]     = Ah[1];
            r0[colw + 4] = Ah[2];
            r1[colw + 4] = Ah[3];
        }

        // ---- PV: warp's 16 tokens x all 64 d, 1-term Ph·Vh ----
#pragma unroll
        for (int jp = 0; jp < 4; jp++) {
            unsigned b0, b1, b2, b3;
            LDSM_X4_T(b0, b1, b2, b3, vh_base + bufoff + jp * 32u);
            MMA16816(O[2 * jp],     Ah[0], Ah[1], Ah[2], Ah[3], b0, b1);
            MMA16816(O[2 * jp + 1], Ah[0], Ah[1], Ah[2], Ah[3], b2, b3);
        }
    }

    // ================= rowsums ================================================
    rs0 += __shfl_xor_sync(0xffffffff, rs0, 1);
    rs0 += __shfl_xor_sync(0xffffffff, rs0, 2);
    rs1 += __shfl_xor_sync(0xffffffff, rs1, 1);
    rs1 += __shfl_xor_sync(0xffffffff, rs1, 2);

    __syncthreads();   // last-stage LDSM reads done before O-red overlays buffers

    if (tg == 0) {
        smem[OFF_PART + (m * 16 + g) * 8 + wi]     = rs0;
        smem[OFF_PART + (m * 16 + g + 8) * 8 + wi] = rs1;
    }
    {
        float* base = smem + OFF_RED + warp * (16 * REDSTR);
#pragma unroll
        for (int j = 0; j < 8; j++) {
            *(float2*)(base + g * REDSTR + j * 8 + 2 * tg)       = make_float2(O[j][0], O[j][1]);
            *(float2*)(base + (g + 8) * REDSTR + j * 8 + 2 * tg) = make_float2(O[j][2], O[j][3]);
        }
    }
    __syncthreads();

    if (tid < TQ) {
        float s = 0.f;
#pragma unroll
        for (int i = 0; i < 8; i++) s += smem[OFF_PART + tid * 8 + i];
        smem[OFF_INV + tid] = 1.0f / s;
    }
    __syncthreads();

    // ================= reduce O partials, write p_val =========================
    {
        int row = tid >> 4;               // 0..31
        int d0  = (tid & 15) * 4;
        int mh  = row >> 4;               // which m-half
        int rl  = row & 15;               // local row within half
        float4 acc = make_float4(0.f, 0.f, 0.f, 0.f);
#pragma unroll
        for (int w = 0; w < 8; w++) {
            float4 v = *(const float4*)(smem + OFF_RED + (mh * 8 + w) * (16 * REDSTR) + rl * REDSTR + d0);
            acc.x += v.x; acc.y += v.y; acc.z += v.z; acc.w += v.w;
        }
        float inv = smem[OFF_INV + row];
        acc.x *= inv; acc.y *= inv; acc.z *= inv; acc.w *= inv;
        __stcs((float4*)(p_val + ((size_t)bh * S_LEN + q0 + row) * D_DIM + d0), acc);
    }

    // ================= write normalized p_attn from fp16 Stile ================
    {
        float* out = p_attn + ((size_t)bh * S_LEN + q0) * S_LEN;
#pragma unroll 8
        for (int i = 0; i < 32; i++) {
            int idx = tid + i * NTHR;         // 0..16383 float4 units
            int row = idx >> 9;               // 512 float4 per row
            int c4  = idx & 511;
            uint2 hw = *(const uint2*)(stf + row * STFSTR + c4 * 2);
            __half2 a = *reinterpret_cast<__half2*>(&hw.x);
            __half2 b = *reinterpret_cast<__half2*>(&hw.y);
            float inv = smem[OFF_INV + row];
            float4 v = make_float4(__low2float(a) * inv, __high2float(a) * inv,
                                   __low2float(b) * inv, __high2float(b) * inv);
            __stcs((float4*)(out + (size_t)row * S_LEN) + c4, v);
        }
    }
}

extern "C" void kernel_launch(void* const* d_in, const int* in_sizes, int n_in,
                              void* d_out, int out_size)
{
    const float*    Q = (const float*)d_in[0];
    const float*    K = (const float*)d_in[1];
    const float*    V = (const float*)d_in[2];
    const unsigned* M = (const unsigned*)d_in[3];

    float* p_val  = (float*)d_out;
    float* p_attn = (float*)d_out + (size_t)2 * 16 * 2048 * 64;

    const size_t smem_bytes = (size_t)SMEM_WORDS * sizeof(float);  // 216192
    cudaFuncSetAttribute(attn_flash_kernel,
                         cudaFuncAttributeMaxDynamicSharedMemorySize,
                         (int)smem_bytes);

    preconvert_kv<<<dim3(128, NBH), 256>>>(K, V);
    pack_mask<<<512, 256>>>(M);
    attn_flash_kernel<<<dim3(S_LEN / TQ, NBH), NTHR, smem_bytes>>>(Q, p_val, p_attn);
}

// round 17
// speedup vs baseline: 1.0471x; 1.0471x over previous
#include <cuda_runtime.h>
#include <cuda_fp16.h>
#include <math.h>

#define S_LEN   2048
#define D_DIM   64
#define TQ      32
#define NBH     32
#define NTHR    512
#define KVSTR   36        // u32 words per token row (32 data + 4 pad; LDSM-clean, 144B rows spread LTS hash)
#define REDSTR  68
#define STFSTR  1036      // u32 (half2) words per Stile row

// ---- main-kernel shared memory word offsets ----
#define OFF_Q    0                     // 32*68 = 2176
#define OFF_STF  2176                  // fp16 Stile: 32*1036 = 33152 u32 words
#define ARR_W    4608                  // 128 tokens * 36 words
#define BUF_W    (2*ARR_W)             // Kh,Vh = 9216 words per buffer
#define OFF_BUF  35328                 // two buffers: 2*9216 = 18432
#define OFF_PART (OFF_BUF + 2*BUF_W)   // 53760 : 32 rows * 8 warps
#define OFF_INV  (OFF_PART + 256)      // 54016 : 32
#define SMEM_WORDS (OFF_INV + 32)      // 54048 words = 216192 bytes
#define OFF_RED  OFF_BUF               // O-reduction overlay: 16 warps*16 rows*68 = 17408 <= 18432

// ---- global scratch (single-fp16 K and V, padded 144B token rows) ----
__device__ __align__(16) unsigned g_Kh[(size_t)NBH * S_LEN * KVSTR];
__device__ __align__(16) unsigned g_Vh[(size_t)NBH * S_LEN * KVSTR];
__device__ unsigned g_mpack[(size_t)S_LEN * (S_LEN / 32)];   // 1 bit per mask elem

static __device__ __forceinline__ unsigned cvt_h2(float x, float y) {
    __half2 hh = __floats2half2_rn(x, y);
    return *reinterpret_cast<unsigned*>(&hh);
}
static __device__ __forceinline__ void cvt_hilo2_f16(float x, float y, unsigned &h, unsigned &l) {
    __half2 hh = __floats2half2_rn(x, y);
    float rx = x - __half2float(__low2half(hh));
    float ry = y - __half2float(__high2half(hh));
    __half2 ll = __floats2half2_rn(rx, ry);
    h = *reinterpret_cast<unsigned*>(&hh);
    l = *reinterpret_cast<unsigned*>(&ll);
}

#define MMA16816(C, A0, A1, A2, A3, B0, B1)                                        \
    asm volatile("mma.sync.aligned.m16n8k16.row.col.f32.f16.f16.f32 "              \
                 "{%0,%1,%2,%3},{%4,%5,%6,%7},{%8,%9},{%0,%1,%2,%3};\n"            \
                 : "+f"(C[0]), "+f"(C[1]), "+f"(C[2]), "+f"(C[3])                  \
                 : "r"(A0), "r"(A1), "r"(A2), "r"(A3), "r"(B0), "r"(B1))

#define LDSM_X4(R0, R1, R2, R3, ADDR)                                              \
    asm volatile("ldmatrix.sync.aligned.m8n8.x4.shared.b16 {%0,%1,%2,%3}, [%4];"  \
                 : "=r"(R0), "=r"(R1), "=r"(R2), "=r"(R3) : "r"(ADDR))

#define LDSM_X4_T(R0, R1, R2, R3, ADDR)                                            \
    asm volatile("ldmatrix.sync.aligned.m8n8.x4.trans.shared.b16 {%0,%1,%2,%3}, [%4];" \
                 : "=r"(R0), "=r"(R1), "=r"(R2), "=r"(R3) : "r"(ADDR))

#define CP_ASYNC16(SADDR, GPTR)                                                    \
    asm volatile("cp.async.cg.shared.global [%0], [%1], 16;\n" :: "r"(SADDR), "l"(GPTR))
#define CP_COMMIT()  asm volatile("cp.async.commit_group;\n")
#define CP_WAIT0()   asm volatile("cp.async.wait_group 0;\n" ::: "memory")

// ===================== pre-pass 1: convert K,V -> fp16 scratch ==================
__global__ void __launch_bounds__(256)
preconvert_kv(const float* __restrict__ K, const float* __restrict__ V)
{
    const int bh  = blockIdx.y;
    const int idx = blockIdx.x * 256 + threadIdx.x;
    const int token = idx >> 4, c4 = idx & 15;
    const size_t tok = (size_t)bh * S_LEN + token;
    const size_t go  = tok * KVSTR + c4 * 2;

    float4 k = __ldg((const float4*)(K + tok * D_DIM) + c4);
    *(uint2*)&g_Kh[go] = make_uint2(cvt_h2(k.x, k.y), cvt_h2(k.z, k.w));
    float4 v = __ldg((const float4*)(V + tok * D_DIM) + c4);
    *(uint2*)&g_Vh[go] = make_uint2(cvt_h2(v.x, v.y), cvt_h2(v.z, v.w));
}

// ===================== pre-pass 2: pack mask to 1 bit/elem ======================
__global__ void __launch_bounds__(256)
pack_mask(const unsigned* __restrict__ M)
{
    const int lane = threadIdx.x & 31;
    const int wglob = (blockIdx.x * 256 + threadIdx.x) >> 5;
    const int nwarps = (gridDim.x * 256) >> 5;
    for (int w = wglob; w < S_LEN * (S_LEN / 32); w += nwarps) {
        unsigned bit = (M[(size_t)w * 32 + lane] != 0u) ? 1u : 0u;
        unsigned word = __ballot_sync(0xffffffffu, bit);
        if (lane == 0) g_mpack[w] = word;
    }
}

// ===================== main fused attention kernel (512 thr, 16 warps) ==========
__global__ void __launch_bounds__(NTHR, 1)
attn_flash_kernel(const float* __restrict__ Q,
                  float* __restrict__ p_val,
                  float* __restrict__ p_attn)
{
    extern __shared__ float smem[];
    unsigned* smw = reinterpret_cast<unsigned*>(smem);
    const unsigned smem_u32 = (unsigned)__cvta_generic_to_shared(smem);

    const int tid  = threadIdx.x;
    const int warp = tid >> 5;          // 0..15
    const int lane = tid & 31;
    const int g    = lane >> 2;
    const int tg   = lane & 3;
    const int m    = warp >> 3;         // m-half: rows m*16 .. m*16+15
    const int wi   = warp & 7;          // token-slice within stage
    const int bh   = blockIdx.y;
    const int q0   = blockIdx.x * TQ;
    const int ln0  = wi * 16;

    // ---- ldmatrix per-lane byte addresses (buffer 0) ----
    const int qk_row  = ln0 + ((lane >> 4) << 3) + (lane & 7);
    const unsigned qk_off = (unsigned)(qk_row * KVSTR + (((lane >> 3) & 1) << 2)) * 4u;
    const unsigned kh_base = smem_u32 + OFF_BUF * 4u + qk_off;
    const int pv_row  = ln0 + (((lane >> 3) & 1) << 3) + (lane & 7);
    const unsigned pv_off = (unsigned)(pv_row * KVSTR + ((lane >> 4) << 2)) * 4u;
    const unsigned vh_base = smem_u32 + (OFF_BUF + ARR_W) * 4u + pv_off;

    // ================= Q tile (32 rows) -> smem -> A fragments (hi/lo fp16) ====
    {
        int row = tid >> 4, c4 = tid & 15;   // 512 threads = 32 rows x 16 f4
        float4 qv = __ldg((const float4*)(Q + ((size_t)bh * S_LEN + q0 + row) * D_DIM) + c4);
        *((float4*)(smem + OFF_Q + row * 68 + c4 * 4)) = qv;
    }
    __syncthreads();

    unsigned qah[4][4], qal[4][4];
    {
        int r0 = m * 16 + g, r1 = m * 16 + g + 8;
#pragma unroll
        for (int ks = 0; ks < 4; ks++) {
            int c = ks * 16 + tg * 2;
            float2 x0 = *(const float2*)(smem + OFF_Q + r0 * 68 + c);
            float2 x1 = *(const float2*)(smem + OFF_Q + r1 * 68 + c);
            float2 x2 = *(const float2*)(smem + OFF_Q + r0 * 68 + c + 8);
            float2 x3 = *(const float2*)(smem + OFF_Q + r1 * 68 + c + 8);
            cvt_hilo2_f16(x0.x, x0.y, qah[ks][0], qal[ks][0]);
            cvt_hilo2_f16(x1.x, x1.y, qah[ks][1], qal[ks][1]);
            cvt_hilo2_f16(x2.x, x2.y, qah[ks][2], qal[ks][2]);
            cvt_hilo2_f16(x3.x, x3.y, qah[ks][3], qal[ks][3]);
        }
    }

    float rs0 = 0.f, rs1 = 0.f;
    float O[8][4];
#pragma unroll
    for (int j = 0; j < 8; j++) { O[j][0] = O[j][1] = O[j][2] = O[j][3] = 0.f; }

    // mask word pointers (rows m*16+g, m*16+g+8; warp's 16 tokens -> word wi>>1)
    const unsigned* mp0 = g_mpack + (size_t)(q0 + m * 16 + g) * 64 + (wi >> 1);
    const unsigned* mp1 = g_mpack + (size_t)(q0 + m * 16 + g + 8) * 64 + (wi >> 1);
    const unsigned posbase = (wi & 1) * 16;
    const size_t bh_base = (size_t)bh * S_LEN * KVSTR;
    unsigned* stf = smw + OFF_STF;

    // ---- prologue: issue stage 0 loads (Kh + Vh) ----
    {
        for (int i = tid; i < ARR_W / 4; i += NTHR) {
            unsigned so = (unsigned)(OFF_BUF * 4 + i * 16);
            CP_ASYNC16(smem_u32 + so,             (const uint4*)(g_Kh + bh_base) + i);
            CP_ASYNC16(smem_u32 + so + ARR_W * 4, (const uint4*)(g_Vh + bh_base) + i);
        }
        CP_COMMIT();
    }

    // =================== pipelined main loop: 16 stages of 128 tokens ==========
    for (int st = 0; st < 16; st++) {
        const int kb0 = st * 128;
        const unsigned bufoff = (unsigned)(st & 1) * (BUF_W * 4);

        CP_WAIT0();
        __syncthreads();   // stage-st data visible; prev compute done

        // ---- prefetch stage st+1 into the other buffer ----
        if (st < 15) {
            const size_t sb = bh_base + (size_t)(kb0 + 128) * KVSTR;
            const unsigned dst = (unsigned)(OFF_BUF * 4) + (unsigned)((st + 1) & 1) * (BUF_W * 4);
            for (int i = tid; i < ARR_W / 4; i += NTHR) {
                unsigned so = dst + (unsigned)i * 16u;
                CP_ASYNC16(smem_u32 + so,             (const uint4*)(g_Kh + sb) + i);
                CP_ASYNC16(smem_u32 + so + ARR_W * 4, (const uint4*)(g_Vh + sb) + i);
            }
            CP_COMMIT();
        }

        // ---- mask words early (hide LDG under tensor work) ----
        unsigned mw0 = __ldg(mp0 + st * 4);
        unsigned mw1 = __ldg(mp1 + st * 4);

        // ---- QK^T: 2-term (Qh + Ql)·Kh with SPLIT accumulator chains ----
        float C0h[4] = {0,0,0,0}, C0l[4] = {0,0,0,0};
        float C1h[4] = {0,0,0,0}, C1l[4] = {0,0,0,0};
#pragma unroll
        for (int ks = 0; ks < 4; ks++) {
            unsigned b0, b1, b2, b3;
            LDSM_X4(b0, b1, b2, b3, kh_base + bufoff + ks * 32u);
            MMA16816(C0h, qah[ks][0], qah[ks][1], qah[ks][2], qah[ks][3], b0, b1);
            MMA16816(C1h, qah[ks][0], qah[ks][1], qah[ks][2], qah[ks][3], b2, b3);
            MMA16816(C0l, qal[ks][0], qal[ks][1], qal[ks][2], qal[ks][3], b0, b1);
            MMA16816(C1l, qal[ks][0], qal[ks][1], qal[ks][2], qal[ks][3], b2, b3);
        }
        float C0[4], C1[4];
#pragma unroll
        for (int i = 0; i < 4; i++) { C0[i] = C0h[i] + C0l[i]; C1[i] = C1h[i] + C1l[i]; }

        // ---- epilogue: mask(bit), exp, rowsum ----
        float e[2][4];
#pragma unroll
        for (int t = 0; t < 2; t++) {
            const float* C = t ? C1 : C0;
            unsigned sh = posbase + t * 8 + tg * 2;
            float* E = e[t];
            E[0] = ((mw0 >> sh) & 1u)       ? 0.f : __expf(C[0] * 0.125f);
            E[1] = ((mw0 >> (sh + 1)) & 1u) ? 0.f : __expf(C[1] * 0.125f);
            E[2] = ((mw1 >> sh) & 1u)       ? 0.f : __expf(C[2] * 0.125f);
            E[3] = ((mw1 >> (sh + 1)) & 1u) ? 0.f : __expf(C[3] * 0.125f);
            rs0 += E[0] + E[1];
            rs1 += E[2] + E[3];
        }

        // ---- E -> A-frag fp16; also store to fp16 Stile (smem) ----
        const int colw = st * 64 + wi * 8 + tg;    // half2 word column
        unsigned Ah[4];
        Ah[0] = cvt_h2(e[0][0], e[0][1]);
        Ah[1] = cvt_h2(e[0][2], e[0][3]);
        Ah[2] = cvt_h2(e[1][0], e[1][1]);
        Ah[3] = cvt_h2(e[1][2], e[1][3]);
        {
            unsigned* r0 = stf + (m * 16 + g) * STFSTR;
            unsigned* r1 = stf + (m * 16 + g + 8) * STFSTR;
            r0[colw]     = Ah[0];
            r1[colw]     = Ah[1];
            r0[colw + 4] = Ah[2];
            r1[colw + 4] = Ah[3];
        }

        // ---- PV: warp's 16 tokens x all 64 d, 1-term Ph·Vh ----
#pragma unroll
        for (int jp = 0; jp < 4; jp++) {
            unsigned b0, b1, b2, b3;
            LDSM_X4_T(b0, b1, b2, b3, vh_base + bufoff + jp * 32u);
            MMA16816(O[2 * jp],     Ah[0], Ah[1], Ah[2], Ah[3], b0, b1);
            MMA16816(O[2 * jp + 1], Ah[0], Ah[1], Ah[2], Ah[3], b2, b3);
        }
    }

    // ================= rowsums ================================================
    rs0 += __shfl_xor_sync(0xffffffff, rs0, 1);
    rs0 += __shfl_xor_sync(0xffffffff, rs0, 2);
    rs1 += __shfl_xor_sync(0xffffffff, rs1, 1);
    rs1 += __shfl_xor_sync(0xffffffff, rs1, 2);

    __syncthreads();   // last-stage LDSM reads done before O-red overlays buffers

    if (tg == 0) {
        smem[OFF_PART + (m * 16 + g) * 8 + wi]     = rs0;
        smem[OFF_PART + (m * 16 + g + 8) * 8 + wi] = rs1;
    }
    {
        float* base = smem + OFF_RED + warp * (16 * REDSTR);
#pragma unroll
        for (int j = 0; j < 8; j++) {
            *(float2*)(base + g * REDSTR + j * 8 + 2 * tg)       = make_float2(O[j][0], O[j][1]);
            *(float2*)(base + (g + 8) * REDSTR + j * 8 + 2 * tg) = make_float2(O[j][2], O[j][3]);
        }
    }
    __syncthreads();

    if (tid < TQ) {
        float s = 0.f;
#pragma unroll
        for (int i = 0; i < 8; i++) s += smem[OFF_PART + tid * 8 + i];
        smem[OFF_INV + tid] = 1.0f / s;
    }
    __syncthreads();

    // ================= reduce O partials, write p_val =========================
    {
        int row = tid >> 4;               // 0..31
        int d0  = (tid & 15) * 4;
        int mh  = row >> 4;               // which m-half
        int rl  = row & 15;               // local row within half
        float4 acc = make_float4(0.f, 0.f, 0.f, 0.f);
#pragma unroll
        for (int w = 0; w < 8; w++) {
            float4 v = *(const float4*)(smem + OFF_RED + (mh * 8 + w) * (16 * REDSTR) + rl * REDSTR + d0);
            acc.x += v.x; acc.y += v.y; acc.z += v.z; acc.w += v.w;
        }
        float inv = smem[OFF_INV + row];
        acc.x *= inv; acc.y *= inv; acc.z *= inv; acc.w *= inv;
        __stcs((float4*)(p_val + ((size_t)bh * S_LEN + q0 + row) * D_DIM + d0), acc);
    }

    // ================= write normalized p_attn from fp16 Stile ================
    {
        float* out = p_attn + ((size_t)bh * S_LEN + q0) * S_LEN;
#pragma unroll 8
        for (int i = 0; i < 32; i++) {
            int idx = tid + i * NTHR;         // 0..16383 float4 units
            int row = idx >> 9;               // 512 float4 per row
            int c4  = idx & 511;
            uint2 hw = *(const uint2*)(stf + row * STFSTR + c4 * 2);
            __half2 a = *reinterpret_cast<__half2*>(&hw.x);
            __half2 b = *reinterpret_cast<__half2*>(&hw.y);
            float inv = smem[OFF_INV + row];
            float4 v = make_float4(__low2float(a) * inv, __high2float(a) * inv,
                                   __low2float(b) * inv, __high2float(b) * inv);
            __stcs((float4*)(out + (size_t)row * S_LEN) + c4, v);
        }
    }
}

extern "C" void kernel_launch(void* const* d_in, const int* in_sizes, int n_in,
                              void* d_out, int out_size)
{
    const float*    Q = (const float*)d_in[0];
    const float*    K = (const float*)d_in[1];
    const float*    V = (const float*)d_in[2];
    const unsigned* M = (const unsigned*)d_in[3];

    float* p_val  = (float*)d_out;
    float* p_attn = (float*)d_out + (size_t)2 * 16 * 2048 * 64;

    const size_t smem_bytes = (size_t)SMEM_WORDS * sizeof(float);  // 216192
    cudaFuncSetAttribute(attn_flash_kernel,
                         cudaFuncAttributeMaxDynamicSharedMemorySize,
                         (int)smem_bytes);

    preconvert_kv<<<dim3(128, NBH), 256>>>(K, V);
    pack_mask<<<512, 256>>>(M);
    attn_flash_kernel<<<dim3(S_LEN / TQ, NBH), NTHR, smem_bytes>>>(Q, p_val, p_attn);
}